// round 6
// baseline (speedup 1.0000x reference)
#include <cuda_runtime.h>

// SimpleSelfAttention: out[b] = (gamma/sigma * (xf xf^T) W + I) @ xf[b]
// B=32, C=64, N=128*128=16384, fp32.
// v2: software-pipelined Gram, higher-occupancy Apply, packed f32x2 FFMA.

#define BATCH  32
#define CH     64
#define NPIX   16384
#define NP2    8192      // NPIX/2 (f32x2 units)
#define SPLITS 64
#define PAIRS  128       // NP2 / SPLITS, pairs per gram block
#define STAGES 8         // PAIRS / 16
#define TSTRIDE 67       // padded tile row stride (u64 units), conflict-free STS

typedef unsigned long long u64;

// scratch: Gram partials (32 MB) and M^T floats (512 KB)
__device__ float g_part[BATCH * SPLITS * CH * CH];
__device__ float g_Mtf[BATCH * CH * CH];

__device__ __forceinline__ u64 ffma2(u64 a, u64 b, u64 c) {
    u64 d;
    asm("fma.rn.f32x2 %0, %1, %2, %3;" : "=l"(d) : "l"(a), "l"(b), "l"(c));
    return d;
}
__device__ __forceinline__ u64 dup2(float f) {
    u64 d;
    asm("mov.b64 %0, {%1, %1};" : "=l"(d) : "f"(f));
    return d;
}

// ---------------------------------------------------------------------------
// Kernel A: Gram partials. grid = BATCH*SPLITS = 2048 blocks, 128 threads.
// Block (b,s): 128 n-pairs. Thread tile 8(c) x 4(d). Double-buffered smem
// stage [16 k-pairs][64 ch] with register-prefetched global loads so LDG
// latency hides behind the 512-FFMA2 compute of the previous stage.
// ---------------------------------------------------------------------------
__global__ __launch_bounds__(128) void gram_kernel(const float* __restrict__ x) {
    __shared__ u64 tile[2][16 * TSTRIDE];
    const u64* xp = reinterpret_cast<const u64*>(x);
    const int b = blockIdx.x >> 6;
    const int s = blockIdx.x & 63;
    const int t = threadIdx.x, tx = t & 15, ty = t >> 4;

    u64 acc[8][4];
#pragma unroll
    for (int i = 0; i < 8; i++)
#pragma unroll
        for (int j = 0; j < 4; j++) acc[i][j] = 0ULL;

    const long base = (long)b * CH * NP2 + s * PAIRS;

    // prefetch stage 0: thread t covers (c = ty+8j, k2 = tx)
    u64 pre[8];
#pragma unroll
    for (int j = 0; j < 8; j++)
        pre[j] = xp[base + (long)(ty + 8 * j) * NP2 + tx];

    for (int st = 0; st < STAGES; st++) {
        const int buf = st & 1;
        // commit prefetched stage to smem
#pragma unroll
        for (int j = 0; j < 8; j++)
            tile[buf][tx * TSTRIDE + ty + 8 * j] = pre[j];
        // issue next stage's global loads (consumed next iteration)
        if (st < STAGES - 1) {
#pragma unroll
            for (int j = 0; j < 8; j++)
                pre[j] = xp[base + (long)(ty + 8 * j) * NP2 + (st + 1) * 16 + tx];
        }
        __syncthreads();
#pragma unroll
        for (int k2 = 0; k2 < 16; k2++) {
            u64 va[8], vb[4];
#pragma unroll
            for (int i = 0; i < 8; i++) va[i] = tile[buf][k2 * TSTRIDE + 8 * ty + i];
#pragma unroll
            for (int j = 0; j < 4; j++) vb[j] = tile[buf][k2 * TSTRIDE + tx + 16 * j];
#pragma unroll
            for (int i = 0; i < 8; i++)
#pragma unroll
                for (int j = 0; j < 4; j++)
                    acc[i][j] = ffma2(va[i], vb[j], acc[i][j]);
        }
    }

    float* gp = g_part + (((long)b * SPLITS + s) << 12);
#pragma unroll
    for (int i = 0; i < 8; i++)
#pragma unroll
        for (int j = 0; j < 4; j++) {
            float2 v = *reinterpret_cast<float2*>(&acc[i][j]);
            gp[(8 * ty + i) * 64 + tx + 16 * j] = v.x + v.y;
        }
}

// ---------------------------------------------------------------------------
// Kernel B: reduce Gram partials, power-iteration sigma, build
// Mtf[b][d][c] = (gamma/sigma) * sum_e xxT[c][e] W[e][d] + (c==d).
// grid = BATCH, 256 threads.
// ---------------------------------------------------------------------------
__global__ void make_M_kernel(const float* __restrict__ Wg,
                              const float* __restrict__ gamma,
                              const float* __restrict__ ug) {
    __shared__ float sW[4096];
    __shared__ float sG[4096];
    __shared__ float sv[64], swv[64], su[64];
    __shared__ float s_inv, s_scale;

    const int b = blockIdx.x, t = threadIdx.x;

    for (int i = t; i < 4096; i += 256) sW[i] = Wg[i];
    if (t < 64) su[t] = ug[t];
    for (int i = t; i < 4096; i += 256) {
        float a = 0.f;
        const float* p = g_part + ((long)b * SPLITS << 12) + i;
#pragma unroll
        for (int s = 0; s < SPLITS; s++) a += p[s * 4096];
        sG[i] = a;
    }
    __syncthreads();

    // v = l2norm(W^T u)
    if (t < 64) {
        float a = 0.f;
        for (int r = 0; r < 64; r++) a += sW[r * 64 + t] * su[r];
        sv[t] = a;
    }
    __syncthreads();
    if (t == 0) {
        float n2 = 0.f;
        for (int c = 0; c < 64; c++) n2 += sv[c] * sv[c];
        s_inv = 1.f / fmaxf(sqrtf(n2), 1e-12f);
    }
    __syncthreads();
    // wv = W @ v_normalized
    if (t < 64) {
        float a = 0.f;
        for (int c = 0; c < 64; c++) a += sW[t * 64 + c] * (sv[c] * s_inv);
        swv[t] = a;
    }
    __syncthreads();
    if (t == 0) {
        float n2 = 0.f;
        for (int r = 0; r < 64; r++) n2 += swv[r] * swv[r];
        float nw = sqrtf(n2);
        float sigma = n2 / fmaxf(nw, 1e-12f);   // u2 @ (W v), exactly as reference
        s_scale = gamma[0] / sigma;
    }
    __syncthreads();

    for (int idx = t; idx < 4096; idx += 256) {
        int d = idx & 63, c = idx >> 6;
        float a = 0.f;
        for (int e = 0; e < 64; e++) a += sG[c * 64 + e] * sW[e * 64 + d];
        g_Mtf[((long)b << 12) + d * 64 + c] = s_scale * a + ((c == d) ? 1.f : 0.f);
    }
}

// ---------------------------------------------------------------------------
// Kernel C: out[b] = M[b] @ xf[b] (identity folded in). grid = BATCH*128
// blocks (64 n-pairs = 128 cols each), 256 threads. Thread tile 4(c) x
// 4(n-pairs) -> acc only 32 regs => 3-4 blocks/SM. M rows broadcast from
// smem floats (dup'd to f32x2 on the fly), x loads stride-1.
// smem: 16KB M + 32KB x = 48KB.
// ---------------------------------------------------------------------------
__global__ __launch_bounds__(256) void apply_kernel(const float* __restrict__ x,
                                                    float* __restrict__ out) {
    __shared__ float sM[4096];     // sM[d*64 + c]
    __shared__ u64 sx[4096];       // sx[d*64 + p], p = pair idx within chunk
    const u64* xp = reinterpret_cast<const u64*>(x);
    u64* op = reinterpret_cast<u64*>(out);

    const int b = blockIdx.x >> 7;
    const int chunk = blockIdx.x & 127;
    const int t = threadIdx.x, tx = t & 15, ty = t >> 4;   // ty 0..15

#pragma unroll
    for (int i = t; i < 4096; i += 256) sM[i] = g_Mtf[((long)b << 12) + i];

    const long nb = (long)b * CH * NP2 + chunk * 64;
#pragma unroll
    for (int l = t; l < 4096; l += 256) {
        int d = l >> 6, p = l & 63;
        sx[l] = xp[nb + (long)d * NP2 + p];
    }
    __syncthreads();

    u64 acc[4][4];
#pragma unroll
    for (int i = 0; i < 4; i++)
#pragma unroll
        for (int j = 0; j < 4; j++) acc[i][j] = 0ULL;

#pragma unroll 8
    for (int d = 0; d < 64; d++) {
        u64 va[4], vb[4];
#pragma unroll
        for (int i = 0; i < 4; i++) va[i] = dup2(sM[d * 64 + 4 * ty + i]);
#pragma unroll
        for (int j = 0; j < 4; j++) vb[j] = sx[d * 64 + tx + 16 * j];
#pragma unroll
        for (int i = 0; i < 4; i++)
#pragma unroll
            for (int j = 0; j < 4; j++)
                acc[i][j] = ffma2(va[i], vb[j], acc[i][j]);
    }

#pragma unroll
    for (int i = 0; i < 4; i++)
#pragma unroll
        for (int j = 0; j < 4; j++)
            op[nb + (long)(4 * ty + i) * NP2 + tx + 16 * j] = acc[i][j];
}

// ---------------------------------------------------------------------------
extern "C" void kernel_launch(void* const* d_in, const int* in_sizes, int n_in,
                              void* d_out, int out_size) {
    const float* x     = (const float*)d_in[0];
    const float* W     = (const float*)d_in[1];
    const float* gamma = (const float*)d_in[2];
    const float* u     = (const float*)d_in[3];
    float* out = (float*)d_out;

    gram_kernel<<<BATCH * SPLITS, 128>>>(x);
    make_M_kernel<<<BATCH, 256>>>(W, gamma, u);
    apply_kernel<<<BATCH * 128, 256>>>(x, out);
}

// round 12
// speedup vs baseline: 1.3751x; 1.3751x over previous
#include <cuda_runtime.h>
#include <cstdint>

// SimpleSelfAttention: out[b] = (gamma/sigma * (xf xf^T) W + I) @ xf[b]
// B=32, C=64, N=128*128=16384, fp32.
// v3: R2 base + cp.async-pipelined Gram + retiled high-occupancy Apply.

#define BATCH  32
#define CH     64
#define NPIX   16384
#define NP2    8192      // NPIX/2 (f32x2 units)
#define SPLITS 16
#define STAGES 32        // (NP2/SPLITS)/16 stages of 16 k2-pairs
#define TS     66        // tile row stride (u64), conflict-free

typedef unsigned long long u64;

// scratch: Gram partials (8 MB) and duplicated-f32x2 M^T (1 MB)
__device__ float g_part[BATCH * SPLITS * CH * CH];
__device__ u64   g_Mt[BATCH * CH * CH];

__device__ __forceinline__ u64 ffma2(u64 a, u64 b, u64 c) {
    u64 d;
    asm("fma.rn.f32x2 %0, %1, %2, %3;" : "=l"(d) : "l"(a), "l"(b), "l"(c));
    return d;
}
__device__ __forceinline__ uint32_t smem_u32(const void* p) {
    uint32_t a;
    asm("{ .reg .u64 t; cvta.to.shared.u64 t, %1; cvt.u32.u64 %0, t; }"
        : "=r"(a) : "l"(p));
    return a;
}
__device__ __forceinline__ void cp8(uint32_t dst, const void* src) {
    asm volatile("cp.async.ca.shared.global [%0], [%1], 8;" :: "r"(dst), "l"(src) : "memory");
}
__device__ __forceinline__ void cpcommit() {
    asm volatile("cp.async.commit_group;" ::: "memory");
}
template <int N>
__device__ __forceinline__ void cpwait() {
    asm volatile("cp.async.wait_group %0;" :: "n"(N) : "memory");
}

// ---------------------------------------------------------------------------
// Kernel A: Gram partials. grid = BATCH*SPLITS = 512 blocks, 128 threads.
// Block (b,s): 512 n-pairs, split in 32 stages of 16 k2-pairs. Thread tile
// 8(c) x 4(d) f32x2. Stage tile [16 k2][64 ch] double-buffered, filled by
// cp.async (8B) so LDG latency hides behind the previous stage's 512 FFMA2s.
// ---------------------------------------------------------------------------
__global__ __launch_bounds__(128) void gram_kernel(const float* __restrict__ x) {
    __shared__ u64 tile[2][16 * TS];
    const u64* xp = reinterpret_cast<const u64*>(x);
    const int b = blockIdx.x >> 4;
    const int s = blockIdx.x & 15;
    const int t = threadIdx.x, tx = t & 15, ty = t >> 4;   // tx: k2, ty: c-group

    u64 acc[8][4];
#pragma unroll
    for (int i = 0; i < 8; i++)
#pragma unroll
        for (int j = 0; j < 4; j++) acc[i][j] = 0ULL;

    const long base = (long)b * CH * NP2 + s * (NP2 / SPLITS);
    const u64* src0 = xp + base + (long)ty * NP2 + tx;     // + 8j*NP2 + st*16
    const uint32_t d0 = smem_u32(&tile[0][tx * TS + ty]);  // + j*64 bytes
    const uint32_t d1 = smem_u32(&tile[1][tx * TS + ty]);

    // prologue: stage 0 into buf 0
#pragma unroll
    for (int j = 0; j < 8; j++) cp8(d0 + j * 64, src0 + (long)(8 * j) * NP2);
    cpcommit();

    for (int st = 0; st < STAGES; st++) {
        const int buf = st & 1;
        if (st < STAGES - 1) {
            const uint32_t dn = (buf ? d0 : d1);
#pragma unroll
            for (int j = 0; j < 8; j++)
                cp8(dn + j * 64, src0 + (long)(8 * j) * NP2 + (st + 1) * 16);
            cpcommit();
            cpwait<1>();
        } else {
            cpwait<0>();
        }
        __syncthreads();
#pragma unroll
        for (int k2 = 0; k2 < 16; k2++) {
            u64 va[8], vb[4];
#pragma unroll
            for (int i = 0; i < 8; i++) va[i] = tile[buf][k2 * TS + 8 * ty + i];
#pragma unroll
            for (int j = 0; j < 4; j++) vb[j] = tile[buf][k2 * TS + tx + 16 * j];
#pragma unroll
            for (int i = 0; i < 8; i++)
#pragma unroll
                for (int j = 0; j < 4; j++)
                    acc[i][j] = ffma2(va[i], vb[j], acc[i][j]);
        }
        __syncthreads();
    }

    float* gp = g_part + (((long)b * SPLITS + s) << 12);
#pragma unroll
    for (int i = 0; i < 8; i++)
#pragma unroll
        for (int j = 0; j < 4; j++) {
            float2 v = *reinterpret_cast<float2*>(&acc[i][j]);
            gp[(8 * ty + i) * 64 + tx + 16 * j] = v.x + v.y;
        }
}

// ---------------------------------------------------------------------------
// Kernel B: reduce Gram partials, power-iteration sigma, build
// Mt[b][d][c] = (gamma/sigma) * sum_e xxT[c][e] W[e][d] + (c==d),
// stored duplicated into both f32x2 lanes. grid = BATCH, 256 threads.
// ---------------------------------------------------------------------------
__global__ void make_M_kernel(const float* __restrict__ Wg,
                              const float* __restrict__ gamma,
                              const float* __restrict__ ug) {
    __shared__ float sW[4096];
    __shared__ float sG[4096];
    __shared__ float sv[64], swv[64], su[64];
    __shared__ float s_inv, s_scale;

    const int b = blockIdx.x, t = threadIdx.x;

    for (int i = t; i < 4096; i += 256) sW[i] = Wg[i];
    if (t < 64) su[t] = ug[t];
    for (int i = t; i < 4096; i += 256) {
        float a = 0.f;
        const float* p = g_part + ((long)b * SPLITS << 12) + i;
#pragma unroll
        for (int s = 0; s < SPLITS; s++) a += p[s * 4096];
        sG[i] = a;
    }
    __syncthreads();

    // v = l2norm(W^T u)
    if (t < 64) {
        float a = 0.f;
        for (int r = 0; r < 64; r++) a += sW[r * 64 + t] * su[r];
        sv[t] = a;
    }
    __syncthreads();
    if (t == 0) {
        float n2 = 0.f;
        for (int c = 0; c < 64; c++) n2 += sv[c] * sv[c];
        s_inv = 1.f / fmaxf(sqrtf(n2), 1e-12f);
    }
    __syncthreads();
    // wv = W @ v_normalized
    if (t < 64) {
        float a = 0.f;
        for (int c = 0; c < 64; c++) a += sW[t * 64 + c] * (sv[c] * s_inv);
        swv[t] = a;
    }
    __syncthreads();
    if (t == 0) {
        float n2 = 0.f;
        for (int r = 0; r < 64; r++) n2 += swv[r] * swv[r];
        float nw = sqrtf(n2);
        float sigma = n2 / fmaxf(nw, 1e-12f);   // u2 @ (W v), exactly as reference
        s_scale = gamma[0] / sigma;
    }
    __syncthreads();

    for (int idx = t; idx < 4096; idx += 256) {
        int d = idx & 63, c = idx >> 6;
        float a = 0.f;
        for (int e = 0; e < 64; e++) a += sG[c * 64 + e] * sW[e * 64 + d];
        float val = s_scale * a + ((c == d) ? 1.f : 0.f);
        unsigned int fb = __float_as_uint(val);
        g_Mt[((long)b << 12) + d * 64 + c] = ((u64)fb << 32) | fb;
    }
}

// ---------------------------------------------------------------------------
// Kernel C: out[b] = M[b] @ xf[b] (identity folded in). grid = BATCH*128
// blocks (64 n-pairs = 128 cols each), 256 threads. Thread tile 4(c) x
// 4(n-pairs) -> acc 32 regs. M pre-duplicated u64 (no per-iter movs),
// loaded in two 32-d halves so smem = 32KB x + 16KB M = 48KB static.
// 3 blocks/SM -> 24 warps.
// ---------------------------------------------------------------------------
__global__ __launch_bounds__(256) void apply_kernel(const float* __restrict__ x,
                                                    float* __restrict__ out) {
    __shared__ u64 sx[4096];      // sx[d*64 + p], 32KB
    __shared__ u64 sMt[2048];     // half of Mt: sMt[dd*64 + c], 16KB
    u64* op = reinterpret_cast<u64*>(out);

    const int b = blockIdx.x >> 7;
    const int chunk = blockIdx.x & 127;
    const int t = threadIdx.x, tx = t & 15, ty = t >> 4;   // ty 0..15

    const long nb = (long)b * CH * NP2 + chunk * 64;

    // load x tile: 4096 u64 via 2048 16B loads
    {
        const float4* xp4 = reinterpret_cast<const float4*>(x);
        float4* sx4 = reinterpret_cast<float4*>(sx);
        const long nb4 = nb >> 1;                    // float4 units, NP2/2 per row
#pragma unroll
        for (int l = t; l < 2048; l += 256) {
            int d = l >> 5, pp = l & 31;
            sx4[d * 32 + pp] = xp4[nb4 + (long)d * (NP2 / 2) + pp];
        }
    }

    u64 acc[4][4];
#pragma unroll
    for (int i = 0; i < 4; i++)
#pragma unroll
        for (int j = 0; j < 4; j++) acc[i][j] = 0ULL;

#pragma unroll
    for (int half = 0; half < 2; half++) {
        // load 32-d half of Mt (u64, pre-duplicated)
#pragma unroll
        for (int l = t; l < 2048; l += 256)
            sMt[l] = g_Mt[((long)b << 12) + (half << 11) + l];
        __syncthreads();

#pragma unroll 8
        for (int dd = 0; dd < 32; dd++) {
            u64 va[4], vb[4];
#pragma unroll
            for (int i = 0; i < 4; i++) va[i] = sMt[dd * 64 + 4 * ty + i];
#pragma unroll
            for (int j = 0; j < 4; j++) vb[j] = sx[(half * 32 + dd) * 64 + tx + 16 * j];
#pragma unroll
            for (int i = 0; i < 4; i++)
#pragma unroll
                for (int j = 0; j < 4; j++)
                    acc[i][j] = ffma2(va[i], vb[j], acc[i][j]);
        }
        __syncthreads();
    }

#pragma unroll
    for (int i = 0; i < 4; i++)
#pragma unroll
        for (int j = 0; j < 4; j++)
            op[nb + (long)(4 * ty + i) * NP2 + tx + 16 * j] = acc[i][j];
}

// ---------------------------------------------------------------------------
extern "C" void kernel_launch(void* const* d_in, const int* in_sizes, int n_in,
                              void* d_out, int out_size) {
    const float* x     = (const float*)d_in[0];
    const float* W     = (const float*)d_in[1];
    const float* gamma = (const float*)d_in[2];
    const float* u     = (const float*)d_in[3];
    float* out = (float*)d_out;

    gram_kernel<<<BATCH * SPLITS, 128>>>(x);
    make_M_kernel<<<BATCH, 256>>>(W, gamma, u);
    apply_kernel<<<BATCH * 128, 256>>>(x, out);
}